// round 3
// baseline (speedup 1.0000x reference)
#include <cuda_runtime.h>

#define EPSI 1e-7f

// ---------------------------------------------------------------------------
// Scratch (B*nh*W*H*d = 4*8*128*128*64 = 33,554,432 floats = 128 MiB each).
// Q,K,V stored as [B][nh][W][H][d]; XV stored as [B][nh][H][W][d].
// ---------------------------------------------------------------------------
__device__ float g_Q[33554432];
__device__ float g_K[33554432];
__device__ float g_V[33554432];
__device__ float g_XV[33554432];

// ---------------------------------------------------------------------------
// Projection GEMM: out[pix][f] = sum_c x[pix][c] * W[c][f] + bias[f]
// M=65536, N=512, K=512.  BM=BN=64, BK=16, 256 threads, 4x4 micro-tile.
// blockIdx.z selects which projection (0=Q, 1=K, 2=V).
// Output written directly into the [B][nh][W][H][d] layout.
// ---------------------------------------------------------------------------
__global__ void __launch_bounds__(256) proj_kernel(
    const float* __restrict__ x,
    const float* __restrict__ wq, const float* __restrict__ bq,
    const float* __restrict__ wk, const float* __restrict__ bk,
    const float* __restrict__ wv, const float* __restrict__ bv)
{
    __shared__ float As[16][65];   // [k][m], padded
    __shared__ float Bs[16][64];   // [k][f]

    const int which = blockIdx.z;
    const float* __restrict__ Wm   = (which == 0) ? wq : (which == 1) ? wk : wv;
    const float* __restrict__ bias = (which == 0) ? bq : (which == 1) ? bk : bv;
    float* __restrict__ outp       = (which == 0) ? g_Q : (which == 1) ? g_K : g_V;

    const int tid = threadIdx.x;
    const int tx  = tid & 15;
    const int ty  = tid >> 4;
    const int m0  = blockIdx.x * 64;   // pixel tile
    const int n0  = blockIdx.y * 64;   // channel (f) tile: exactly one head

    // A-tile load mapping: thread -> (row m, 4 consecutive k)
    const int am = tid >> 2;
    const int ak = (tid & 3) * 4;
    // B-tile load mapping: thread -> (row k, 4 consecutive f)
    const int bkr = tid >> 4;
    const int bfc = (tid & 15) * 4;

    float acc[4][4] = {};

    for (int k0 = 0; k0 < 512; k0 += 16) {
        float4 a4 = *(const float4*)(x + (m0 + am) * 512 + k0 + ak);
        As[ak + 0][am] = a4.x;
        As[ak + 1][am] = a4.y;
        As[ak + 2][am] = a4.z;
        As[ak + 3][am] = a4.w;
        *(float4*)(&Bs[bkr][bfc]) = *(const float4*)(Wm + (k0 + bkr) * 512 + n0 + bfc);
        __syncthreads();
#pragma unroll
        for (int kk = 0; kk < 16; kk++) {
            float a0 = As[kk][ty * 4 + 0];
            float a1 = As[kk][ty * 4 + 1];
            float a2 = As[kk][ty * 4 + 2];
            float a3 = As[kk][ty * 4 + 3];
            float4 b4 = *(const float4*)(&Bs[kk][tx * 4]);
            acc[0][0] += a0 * b4.x; acc[0][1] += a0 * b4.y; acc[0][2] += a0 * b4.z; acc[0][3] += a0 * b4.w;
            acc[1][0] += a1 * b4.x; acc[1][1] += a1 * b4.y; acc[1][2] += a1 * b4.z; acc[1][3] += a1 * b4.w;
            acc[2][0] += a2 * b4.x; acc[2][1] += a2 * b4.y; acc[2][2] += a2 * b4.z; acc[2][3] += a2 * b4.w;
            acc[3][0] += a3 * b4.x; acc[3][1] += a3 * b4.y; acc[3][2] += a3 * b4.z; acc[3][3] += a3 * b4.w;
        }
        __syncthreads();
    }

    // Epilogue: bias + scatter into [B][nh][W][H][d]
    const int n  = n0 >> 6;        // head index (BN=64 == d, so one head per CTA)
    const int dd = tx * 4;
    float4 bb;
    bb.x = bias[n0 + dd + 0];
    bb.y = bias[n0 + dd + 1];
    bb.z = bias[n0 + dd + 2];
    bb.w = bias[n0 + dd + 3];
#pragma unroll
    for (int i = 0; i < 4; i++) {
        const int pix = m0 + ty * 4 + i;
        const int b = pix >> 14;
        const int h = (pix >> 7) & 127;
        const int w = pix & 127;
        const int base = (((b * 8 + n) * 128 + w) * 128 + h) * 64;
        float4 o;
        o.x = acc[i][0] + bb.x;
        o.y = acc[i][1] + bb.y;
        o.z = acc[i][2] + bb.z;
        o.w = acc[i][3] + bb.w;
        *(float4*)(outp + base + dd) = o;
    }
}

// ---------------------------------------------------------------------------
// Axial attention, one CTA per (b, head, line).
//   stage 1 (columns): line = w.  Q/K/V blocks contiguous in [B][nh][W][H][d].
//                      Output -> g_XV in [B][nh][H][W][d].
//   stage 2 (rows):    line = h.  Q/K rows strided (8192 floats), XV block
//                      contiguous.  Output -> d_out [B,H,W,512], c = d*8 + n.
// 256 threads; S computed with 8x8 micro-tiles; softmax per row by warps;
// O = S*V with 8x4 micro-tiles.
// ---------------------------------------------------------------------------
__global__ void __launch_bounds__(256) attn_kernel(float* __restrict__ out, const int stage)
{
    extern __shared__ float smem[];
    float* S   = smem;            // 128*128 = 16384
    float* Qs  = smem + 16384;    // 128*64  =  8192  ([row][d])
    float* KsT = smem + 24576;    // 64*132  =  8448  ([d][row], padded)
    float* Vs  = smem + 33024;    // 128*64  =  8192  ([row][d])

    const int tid = threadIdx.x;
    const int x_  = blockIdx.x;                    // w (stage1) or h (stage2)
    const int b8n = blockIdx.z * 8 + blockIdx.y;   // b*8 + n

    const float* __restrict__ Qg = g_Q;
    const float* __restrict__ Kg = g_K;
    const float* __restrict__ Vg = (stage == 1) ? g_V : g_XV;

    int qbase, rstride, vbase;
    if (stage == 1) {
        qbase   = (b8n * 128 + x_) * 8192;
        rstride = 64;
        vbase   = qbase;
    } else {
        qbase   = b8n * 1048576 + x_ * 64;
        rstride = 8192;
        vbase   = (b8n * 128 + x_) * 8192;
    }

    // ---- load Q (natural), K (transposed), V (natural) ----
    for (int idx = tid; idx < 2048; idx += 256) {
        const int dd4 = (idx & 15) * 4;
        const int row = idx >> 4;
        const int goff = qbase + row * rstride + dd4;
        float4 q4 = *(const float4*)(Qg + goff);
        *(float4*)(Qs + row * 64 + dd4) = q4;
        float4 k4 = *(const float4*)(Kg + goff);
        KsT[(dd4 + 0) * 132 + row] = k4.x;
        KsT[(dd4 + 1) * 132 + row] = k4.y;
        KsT[(dd4 + 2) * 132 + row] = k4.z;
        KsT[(dd4 + 3) * 132 + row] = k4.w;
        *(float4*)(Vs + idx * 4) = *(const float4*)(Vg + vbase + idx * 4);
    }
    __syncthreads();

    // ---- S = Q * K^T, clip(+-(1-eps)), * 1/8 ----
    const int tx = tid & 15, ty = tid >> 4;
    const int ri = ty * 8, cj = tx * 8;
    {
        float acc[8][8] = {};
#pragma unroll 8
        for (int kk = 0; kk < 64; kk++) {
            float a[8];
#pragma unroll
            for (int i = 0; i < 8; i++) a[i] = Qs[(ri + i) * 64 + kk];
            float4 b0 = *(const float4*)(KsT + kk * 132 + cj);
            float4 b1 = *(const float4*)(KsT + kk * 132 + cj + 4);
            float bb[8] = { b0.x, b0.y, b0.z, b0.w, b1.x, b1.y, b1.z, b1.w };
#pragma unroll
            for (int i = 0; i < 8; i++)
#pragma unroll
                for (int j = 0; j < 8; j++)
                    acc[i][j] += a[i] * bb[j];
        }
        const float lo = -1.0f + EPSI, hi = 1.0f - EPSI;
#pragma unroll
        for (int i = 0; i < 8; i++) {
#pragma unroll
            for (int j = 0; j < 8; j++) {
                S[(ri + i) * 128 + cj + j] =
                    fminf(fmaxf(acc[i][j], lo), hi) * 0.125f;
            }
        }
    }
    __syncthreads();

    // ---- row-wise softmax (fp32), clip [eps, 1-eps] ----
    {
        const int wid = tid >> 5, lane = tid & 31;
        for (int rr = 0; rr < 16; rr++) {
            float* srow = S + (wid * 16 + rr) * 128;
            float v0 = srow[lane];
            float v1 = srow[lane + 32];
            float v2 = srow[lane + 64];
            float v3 = srow[lane + 96];
            float mx = fmaxf(fmaxf(v0, v1), fmaxf(v2, v3));
#pragma unroll
            for (int off = 16; off; off >>= 1)
                mx = fmaxf(mx, __shfl_xor_sync(0xffffffffu, mx, off));
            float e0 = __expf(v0 - mx);
            float e1 = __expf(v1 - mx);
            float e2 = __expf(v2 - mx);
            float e3 = __expf(v3 - mx);
            float s = e0 + e1 + e2 + e3;
#pragma unroll
            for (int off = 16; off; off >>= 1)
                s += __shfl_xor_sync(0xffffffffu, s, off);
            const float inv = 1.0f / s;
            const float alo = EPSI, ahi = 1.0f - EPSI;
            srow[lane]      = fminf(fmaxf(e0 * inv, alo), ahi);
            srow[lane + 32] = fminf(fmaxf(e1 * inv, alo), ahi);
            srow[lane + 64] = fminf(fmaxf(e2 * inv, alo), ahi);
            srow[lane + 96] = fminf(fmaxf(e3 * inv, alo), ahi);
        }
    }
    __syncthreads();

    // ---- O = S * V  (128x64), thread tile 8 rows x 4 cols ----
    float o[8][4] = {};
#pragma unroll 4
    for (int kk = 0; kk < 128; kk++) {
        float4 vv = *(const float4*)(Vs + kk * 64 + tx * 4);
#pragma unroll
        for (int i = 0; i < 8; i++) {
            float a = S[(ri + i) * 128 + kk];
            o[i][0] += a * vv.x;
            o[i][1] += a * vv.y;
            o[i][2] += a * vv.z;
            o[i][3] += a * vv.w;
        }
    }

    // ---- epilogue ----
    if (stage == 1) {
        // xv[b][n][h][w][d]: h = ri+i, w = x_, d = tx*4..+3
        const int obase = b8n * 1048576 + x_ * 64 + tx * 4;
#pragma unroll
        for (int i = 0; i < 8; i++) {
            float4 o4 = { o[i][0], o[i][1], o[i][2], o[i][3] };
            *(float4*)(g_XV + obase + (ri + i) * 8192) = o4;
        }
    } else {
        // out[b][h][w][d*8+n]: w = ri+i, d = tx*4..+3, h = x_
        const int n = b8n & 7;
        const int b = b8n >> 3;
        const int obase = (b * 128 + x_) * 65536 + (tx * 4) * 8 + n;
#pragma unroll
        for (int i = 0; i < 8; i++) {
#pragma unroll
            for (int j = 0; j < 4; j++)
                out[obase + (ri + i) * 512 + j * 8] = o[i][j];
        }
    }
}

// ---------------------------------------------------------------------------
extern "C" void kernel_launch(void* const* d_in, const int* in_sizes, int n_in,
                              void* d_out, int out_size)
{
    const float* x  = (const float*)d_in[0];
    const float* wq = (const float*)d_in[1];
    const float* bq = (const float*)d_in[2];
    const float* wk = (const float*)d_in[3];
    const float* bk = (const float*)d_in[4];
    const float* wv = (const float*)d_in[5];
    const float* bv = (const float*)d_in[6];
    float* out = (float*)d_out;

    const int smemA = 41216 * (int)sizeof(float);   // 164,864 B
    cudaFuncSetAttribute((const void*)attn_kernel,
                         cudaFuncAttributeMaxDynamicSharedMemorySize, smemA);

    dim3 pg(1024, 8, 3);
    proj_kernel<<<pg, 256>>>(x, wq, bq, wk, bk, wv, bv);

    dim3 ag(128, 8, 4);
    attn_kernel<<<ag, 256, smemA>>>(out, 1);
    attn_kernel<<<ag, 256, smemA>>>(out, 2);
}